// round 6
// baseline (speedup 1.0000x reference)
#include <cuda_runtime.h>
#include <math.h>

#define TPB 352
typedef unsigned long long u64;

// ---- packed fp32x2 helpers (sm_103a) ----
__device__ __forceinline__ u64 packdup(float a) {
    u64 r; asm("mov.b64 %0,{%1,%1};" : "=l"(r) : "f"(a)); return r;
}
__device__ __forceinline__ u64 fma2(u64 a, u64 b, u64 c) {
    u64 d; asm("fma.rn.f32x2 %0,%1,%2,%3;" : "=l"(d) : "l"(a), "l"(b), "l"(c)); return d;
}
__device__ __forceinline__ void unpk(u64 x, float& lo, float& hi) {
    asm("mov.b64 {%0,%1},%2;" : "=f"(lo), "=f"(hi) : "l"(x));
}

// ---- shared memory layout (floats) ----
#define OFF_W1Q 0        // u64[49 tap][4 pair]            (392 floats)
#define OFF_W2P 392      // [5 pair][8ci][25] x2           (2000)
#define OFF_CWQ 2392     // u64[5 quad][10ci][25 tap][2]   (5000)
#define OFF_B1P 7392     // (8)
#define OFF_B2P 7400     // (10)
#define OFF_CBP 7410     // (20) -> 7430 pad 7432
#define OFF_K1T 7432     // kf_fc1_w^T [90][33]   (2970)
#define OFF_K2T 10402    // kf_fc2_w^T [32][41]   (1312)
#define OFF_F2T 11714    // fc2_w^T    [50][11]   (550) -> 12264 pad 12272
// per-image blocks (x2)
#define SH_IMG0 12272
#define IMG_STRIDE 3176
#define PX   0                // [28][28] (784)
#define PBUF 784              // pooled1 [8][11][12]=1056 / pooled3 [10][13][14]=1820
#define PF   2604             // (90)
#define PH   2694             // (32)
#define PK   2726             // (40) -> 2766 pad 2768
#define PP4  2768             // [20][4][4] (320)
#define PY1  3088             // (64)
#define PLG  3152             // (16) -> 3168
#define SMEM_FLOATS (SH_IMG0 + 2 * IMG_STRIDE)
#define SMEM_BYTES  (SMEM_FLOATS * 4)

__global__ __launch_bounds__(TPB, 3) void fused_net_kernel(
    const float* __restrict__ x,
    const float* __restrict__ kf_w1, const float* __restrict__ kf_b1,
    const float* __restrict__ kf_w2, const float* __restrict__ kf_b2,
    const float* __restrict__ kf_fc1_w, const float* __restrict__ kf_fc1_b,
    const float* __restrict__ kf_fc2_w, const float* __restrict__ kf_fc2_b,
    const float* __restrict__ conv2_w, const float* __restrict__ conv2_b,
    const float* __restrict__ fc1_w, const float* __restrict__ fc1_b,
    const float* __restrict__ fc2_w, const float* __restrict__ fc2_b,
    float* __restrict__ out, int N)
{
    extern __shared__ __align__(16) float s[];

    const int bn  = blockIdx.x;
    const int tid = threadIdx.x;
    const int i0  = 2 * bn;

    // ================= Stage 0: stage inputs into smem =================
    {
        #pragma unroll
        for (int img = 0; img < 2; img++) {
            if (i0 + img < N) {
                const float4* x4 = (const float4*)(x + (i0 + img) * 784);
                float4* sx4 = (float4*)(s + SH_IMG0 + img * IMG_STRIDE + PX);
                for (int i = tid; i < 196; i += TPB) sx4[i] = x4[i];
            }
        }
        // kf_w1 -> u64[49 tap][4 pair]
        for (int i = tid; i < 392; i += TPB) {
            int c = i / 49, q = i - c * 49;
            s[OFF_W1Q + ((q * 4 + (c >> 1)) << 1) + (c & 1)] = kf_w1[i];
        }
        // kf_w2 -> [5 pair][8ci][25] x2
        for (int i = tid; i < 2000; i += TPB) {
            int c = i / 200, r = i - c * 200;
            s[OFF_W2P + (((c >> 1) * 200 + r) << 1) + (c & 1)] = kf_w2[i];
        }
        // conv2_w -> u64[5 quad][250 tap][2 sub]
        for (int i = tid; i < 5000; i += TPB) {
            int c = i / 250, r = i - c * 250;   // c: out ch 0..19, r = ci*25+q
            int cpq = c >> 2, sub = (c >> 1) & 1, lane = c & 1;
            s[OFF_CWQ + cpq * 1000 + r * 4 + sub * 2 + lane] = conv2_w[i];
        }
        if (tid < 8)  s[OFF_B1P + tid] = kf_b1[tid];
        if (tid < 10) s[OFF_B2P + tid] = kf_b2[tid];
        if (tid < 20) s[OFF_CBP + tid] = conv2_b[tid];
        for (int i = tid; i < 2880; i += TPB) {
            int o = i / 90, q = i - o * 90;
            s[OFF_K1T + q * 33 + o] = kf_fc1_w[i];
        }
        for (int i = tid; i < 1280; i += TPB) {
            int o = i >> 5, q = i & 31;
            s[OFF_K2T + q * 41 + o] = kf_fc2_w[i];
        }
        for (int i = tid; i < 500; i += TPB) {
            int o = i / 50, q = i - o * 50;
            s[OFF_F2T + q * 11 + o] = fc2_w[i];
        }
    }
    __syncthreads();

    // ===== Stage 1: conv7x7 (1->8) + pool + relu -> pooled1 [8][11][12pad] =====
    // thread = (img, pooled pos): 242 units, ALL 8 output channels per thread.
    if (tid < 242) {
        const int img = tid / 121;
        const int pos = tid - img * 121;
        const int pi  = pos / 11;
        const int pj  = pos - pi * 11;
        const float* sx = s + SH_IMG0 + img * IMG_STRIDE + PX;
        const ulonglong2* wq = (const ulonglong2*)(s + OFF_W1Q);
        u64 A[4][4];   // [pair][win: h0v0,h1v0,h0v1,h1v1]
        #pragma unroll
        for (int cp = 0; cp < 4; cp++) {
            const u64 b = ((const u64*)(s + OFF_B1P))[cp];
            #pragma unroll
            for (int w = 0; w < 4; w++) A[cp][w] = b;
        }
        #pragma unroll
        for (int r = 0; r < 8; r++) {
            const float2* row = (const float2*)(sx + (2 * pi + r) * 28 + 2 * pj);
            u64 pd[8];
            #pragma unroll
            for (int j = 0; j < 4; j++) {
                float2 f = row[j];
                pd[2 * j]     = packdup(f.x);
                pd[2 * j + 1] = packdup(f.y);
            }
            if (r < 7) {
                #pragma unroll
                for (int v = 0; v < 7; v++) {
                    const ulonglong2 w01 = wq[(r * 7 + v) * 2];
                    const ulonglong2 w23 = wq[(r * 7 + v) * 2 + 1];
                    A[0][0] = fma2(pd[v], w01.x, A[0][0]); A[0][1] = fma2(pd[v + 1], w01.x, A[0][1]);
                    A[1][0] = fma2(pd[v], w01.y, A[1][0]); A[1][1] = fma2(pd[v + 1], w01.y, A[1][1]);
                    A[2][0] = fma2(pd[v], w23.x, A[2][0]); A[2][1] = fma2(pd[v + 1], w23.x, A[2][1]);
                    A[3][0] = fma2(pd[v], w23.y, A[3][0]); A[3][1] = fma2(pd[v + 1], w23.y, A[3][1]);
                }
            }
            if (r >= 1) {
                #pragma unroll
                for (int v = 0; v < 7; v++) {
                    const ulonglong2 w01 = wq[((r - 1) * 7 + v) * 2];
                    const ulonglong2 w23 = wq[((r - 1) * 7 + v) * 2 + 1];
                    A[0][2] = fma2(pd[v], w01.x, A[0][2]); A[0][3] = fma2(pd[v + 1], w01.x, A[0][3]);
                    A[1][2] = fma2(pd[v], w01.y, A[1][2]); A[1][3] = fma2(pd[v + 1], w01.y, A[1][3]);
                    A[2][2] = fma2(pd[v], w23.x, A[2][2]); A[2][3] = fma2(pd[v + 1], w23.x, A[2][3]);
                    A[3][2] = fma2(pd[v], w23.y, A[3][2]); A[3][3] = fma2(pd[v + 1], w23.y, A[3][3]);
                }
            }
        }
        float* buf = s + SH_IMG0 + img * IMG_STRIDE + PBUF;
        #pragma unroll
        for (int cp = 0; cp < 4; cp++) {
            float p0, p1, q0, q1, r0, r1, t0, t1;
            unpk(A[cp][0], p0, p1); unpk(A[cp][1], q0, q1);
            unpk(A[cp][2], r0, r1); unpk(A[cp][3], t0, t1);
            buf[(2 * cp)     * 132 + pi * 12 + pj] =
                fmaxf(fmaxf(fmaxf(p0, q0), fmaxf(r0, t0)), 0.0f);
            buf[(2 * cp + 1) * 132 + pi * 12 + pj] =
                fmaxf(fmaxf(fmaxf(p1, q1), fmaxf(r1, t1)), 0.0f);
        }
    }
    __syncthreads();

    // ===== Stage 2: conv5x5 (8->10) + pool + relu -> f [10][3][3] =====
    if (tid < 192) {
        const int uu   = tid >> 1;
        const int half = tid & 1;
        const bool valid = uu < 90;
        const int u   = valid ? uu : 0;
        const int img = u / 45;
        const int t   = u - img * 45;
        const int cp  = t / 9;
        const int pos = t - cp * 9;
        const int pi  = pos / 3;
        const int pj  = pos - pi * 3;
        const float* buf = s + SH_IMG0 + img * IMG_STRIDE + PBUF;
        const u64 bias = ((const u64*)(s + OFF_B2P))[cp];
        u64 A[4];
        #pragma unroll
        for (int k = 0; k < 4; k++) A[k] = half ? 0ull : bias;
        #pragma unroll
        for (int cc = 0; cc < 4; cc++) {
            const int ci = 4 * half + cc;
            const u64* wp = (const u64*)(s + OFF_W2P) + (cp * 8 + ci) * 25;
            #pragma unroll
            for (int r = 0; r < 6; r++) {
                const float2* row = (const float2*)(buf + ci * 132 + (2 * pi + r) * 12 + 2 * pj);
                u64 pd[6];
                #pragma unroll
                for (int j = 0; j < 3; j++) {
                    float2 f = row[j];
                    pd[2 * j]     = packdup(f.x);
                    pd[2 * j + 1] = packdup(f.y);
                }
                if (r < 5) {
                    #pragma unroll
                    for (int v = 0; v < 5; v++) {
                        const u64 wv = wp[r * 5 + v];
                        A[0] = fma2(pd[v],     wv, A[0]);
                        A[1] = fma2(pd[v + 1], wv, A[1]);
                    }
                }
                if (r >= 1) {
                    #pragma unroll
                    for (int v = 0; v < 5; v++) {
                        const u64 wv = wp[(r - 1) * 5 + v];
                        A[2] = fma2(pd[v],     wv, A[2]);
                        A[3] = fma2(pd[v + 1], wv, A[3]);
                    }
                }
            }
        }
        float me = -INFINITY, mo = -INFINITY;
        #pragma unroll
        for (int k = 0; k < 4; k++) {
            float lo, hi;
            unpk(A[k], lo, hi);
            lo += __shfl_xor_sync(0xffffffffu, lo, 1);
            hi += __shfl_xor_sync(0xffffffffu, hi, 1);
            me = fmaxf(me, lo);
            mo = fmaxf(mo, hi);
        }
        if (valid) {
            float* f = s + SH_IMG0 + img * IMG_STRIDE + PF;
            if (half == 0) f[(2 * cp)     * 9 + pos] = fmaxf(me, 0.0f);
            else           f[(2 * cp + 1) * 9 + pos] = fmaxf(mo, 0.0f);
        }
    }
    __syncthreads();

    // ===== Stage 3a: hypernet fc1 90->32 relu =====
    if (tid < 64) {
        const int img = tid >> 5;
        const int o   = tid & 31;
        const float* f = s + SH_IMG0 + img * IMG_STRIDE + PF;
        float acc = kf_fc1_b[o];
        #pragma unroll 6
        for (int q = 0; q < 90; q++)
            acc = fmaf(f[q], s[OFF_K1T + q * 33 + o], acc);
        s[SH_IMG0 + img * IMG_STRIDE + PH + o] = fmaxf(acc, 0.0f);
    }
    __syncthreads();
    // ===== Stage 3b: hypernet fc2 32->40 =====
    if (tid < 80) {
        const int img = tid / 40;
        const int o   = tid - img * 40;
        const float* h = s + SH_IMG0 + img * IMG_STRIDE + PH;
        float acc = kf_fc2_b[o];
        #pragma unroll
        for (int q = 0; q < 32; q++)
            acc = fmaf(h[q], s[OFF_K2T + q * 41 + o], acc);
        s[SH_IMG0 + img * IMG_STRIDE + PK + o] = acc;
    }
    __syncthreads();

    // ===== Stage 4: dynamic 2x2 conv + pool + relu -> pooled3 [10][13][14pad] =====
    for (int it = tid; it < 3380; it += TPB) {
        const int img = it / 1690;
        const int t   = it - img * 1690;
        const int c   = t / 169;
        const int rem = t - c * 169;
        const int pi  = rem / 13;
        const int pj  = rem - pi * 13;
        const float* base = s + SH_IMG0 + img * IMG_STRIDE;
        const float k00 = base[PK + c * 4 + 0];
        const float k01 = base[PK + c * 4 + 1];
        const float k10 = base[PK + c * 4 + 2];
        const float k11 = base[PK + c * 4 + 3];
        float a[3][3];
        #pragma unroll
        for (int u2 = 0; u2 < 3; u2++) {
            const float2 f01 = *(const float2*)(base + PX + (2 * pi + u2) * 28 + 2 * pj);
            a[u2][0] = f01.x; a[u2][1] = f01.y;
            a[u2][2] = base[PX + (2 * pi + u2) * 28 + 2 * pj + 2];
        }
        float m = -INFINITY;
        #pragma unroll
        for (int di = 0; di < 2; di++)
            #pragma unroll
            for (int dj = 0; dj < 2; dj++) {
                float cv = a[di][dj] * k00;
                cv = fmaf(a[di][dj + 1],     k01, cv);
                cv = fmaf(a[di + 1][dj],     k10, cv);
                cv = fmaf(a[di + 1][dj + 1], k11, cv);
                m = fmaxf(m, cv);
            }
        s[SH_IMG0 + img * IMG_STRIDE + PBUF + c * 182 + pi * 14 + pj] = fmaxf(m, 0.0f);
    }
    __syncthreads();

    // ===== Stage 5: conv5x5 (10->20) + pool + relu -> pooled4 [20][4][4] =====
    // thread = (quad cpq, img, ci-half, pos16): 320 units; 4 output channels each;
    // ci halves combined by shfl_xor(16).
    if (tid < 320) {
        const int cpq = tid >> 6;          // 0..4 (warp-pair uniform)
        const int rem = tid & 63;
        const int img = rem >> 5;
        const int cih = (rem >> 4) & 1;    // lane bit 4 -> shfl_xor(16) partner
        const int pos = rem & 15;
        const int pi  = pos >> 2;
        const int pj  = pos & 3;
        const float* buf = s + SH_IMG0 + img * IMG_STRIDE + PBUF;
        const u64 b0 = ((const u64*)(s + OFF_CBP))[2 * cpq];
        const u64 b1 = ((const u64*)(s + OFF_CBP))[2 * cpq + 1];
        u64 A0[4], A1[4];
        #pragma unroll
        for (int w = 0; w < 4; w++) { A0[w] = cih ? 0ull : b0; A1[w] = cih ? 0ull : b1; }

        #pragma unroll
        for (int cc = 0; cc < 5; cc++) {
            const int ci = 5 * cih + cc;
            const ulonglong2* wq = (const ulonglong2*)(s + OFF_CWQ) + cpq * 250 + ci * 25;
            #pragma unroll
            for (int r = 0; r < 6; r++) {
                const float2* row = (const float2*)(buf + ci * 182 + (2 * pi + r) * 14 + 2 * pj);
                u64 pd[6];
                #pragma unroll
                for (int j = 0; j < 3; j++) {
                    float2 f = row[j];
                    pd[2 * j]     = packdup(f.x);
                    pd[2 * j + 1] = packdup(f.y);
                }
                if (r < 5) {
                    #pragma unroll
                    for (int v = 0; v < 5; v++) {
                        const ulonglong2 w = wq[r * 5 + v];
                        A0[0] = fma2(pd[v],     w.x, A0[0]);
                        A0[1] = fma2(pd[v + 1], w.x, A0[1]);
                        A1[0] = fma2(pd[v],     w.y, A1[0]);
                        A1[1] = fma2(pd[v + 1], w.y, A1[1]);
                    }
                }
                if (r >= 1) {
                    #pragma unroll
                    for (int v = 0; v < 5; v++) {
                        const ulonglong2 w = wq[(r - 1) * 5 + v];
                        A0[2] = fma2(pd[v],     w.x, A0[2]);
                        A0[3] = fma2(pd[v + 1], w.x, A0[3]);
                        A1[2] = fma2(pd[v],     w.y, A1[2]);
                        A1[3] = fma2(pd[v + 1], w.y, A1[3]);
                    }
                }
            }
        }
        float* p4 = s + SH_IMG0 + img * IMG_STRIDE + PP4;
        {
            float m0 = -INFINITY, m1 = -INFINITY;
            #pragma unroll
            for (int w = 0; w < 4; w++) {
                float lo, hi;
                unpk(A0[w], lo, hi);
                lo += __shfl_xor_sync(0xffffffffu, lo, 16);
                hi += __shfl_xor_sync(0xffffffffu, hi, 16);
                m0 = fmaxf(m0, lo);
                m1 = fmaxf(m1, hi);
            }
            if (cih == 0) {
                p4[(4 * cpq)     * 16 + pi * 4 + pj] = fmaxf(m0, 0.0f);
                p4[(4 * cpq + 1) * 16 + pi * 4 + pj] = fmaxf(m1, 0.0f);
            }
        }
        {
            float m0 = -INFINITY, m1 = -INFINITY;
            #pragma unroll
            for (int w = 0; w < 4; w++) {
                float lo, hi;
                unpk(A1[w], lo, hi);
                lo += __shfl_xor_sync(0xffffffffu, lo, 16);
                hi += __shfl_xor_sync(0xffffffffu, hi, 16);
                m0 = fmaxf(m0, lo);
                m1 = fmaxf(m1, hi);
            }
            if (cih == 0) {
                p4[(4 * cpq + 2) * 16 + pi * 4 + pj] = fmaxf(m0, 0.0f);
                p4[(4 * cpq + 3) * 16 + pi * 4 + pj] = fmaxf(m1, 0.0f);
            }
        }
    }
    __syncthreads();

    // ===== Stage 6: fc1 320->50 relu, warp per (img,o) =====
    {
        const int warp = tid >> 5;
        const int lane = tid & 31;
        for (int u = warp; u < 100; u += (TPB / 32)) {
            const int img = u / 50;
            const int o   = u - img * 50;
            const float4* wr = (const float4*)(fc1_w + o * 320);
            const float4* pr = (const float4*)(s + SH_IMG0 + img * IMG_STRIDE + PP4);
            float acc = 0.0f;
            #pragma unroll
            for (int k = 0; k < 3; k++) {
                const int i = lane + 32 * k;
                if (i < 80) {
                    float4 w4 = wr[i];
                    float4 p4 = pr[i];
                    acc = fmaf(w4.x, p4.x, fmaf(w4.y, p4.y,
                          fmaf(w4.z, p4.z, fmaf(w4.w, p4.w, acc))));
                }
            }
            #pragma unroll
            for (int off = 16; off > 0; off >>= 1)
                acc += __shfl_xor_sync(0xffffffffu, acc, off);
            if (lane == 0)
                s[SH_IMG0 + img * IMG_STRIDE + PY1 + o] = fmaxf(acc + fc1_b[o], 0.0f);
        }
    }
    __syncthreads();

    // ===== Stage 7: fc2 50->10 + log_softmax =====
    if (tid < 20) {
        const int img = tid / 10;
        const int o   = tid - img * 10;
        const float* y1 = s + SH_IMG0 + img * IMG_STRIDE + PY1;
        float acc = fc2_b[o];
        #pragma unroll 10
        for (int q = 0; q < 50; q++)
            acc = fmaf(y1[q], s[OFF_F2T + q * 11 + o], acc);
        s[SH_IMG0 + img * IMG_STRIDE + PLG + o] = acc;
    }
    __syncthreads();
    if (tid < 2) {
        const float* lg = s + SH_IMG0 + tid * IMG_STRIDE + PLG;
        float mx = lg[0];
        #pragma unroll
        for (int q = 1; q < 10; q++) mx = fmaxf(mx, lg[q]);
        float sum = 0.0f;
        #pragma unroll
        for (int q = 0; q < 10; q++) sum += expf(lg[q] - mx);
        s[SH_IMG0 + tid * IMG_STRIDE + PLG + 12] = mx + logf(sum);
    }
    __syncthreads();
    if (tid < 20) {
        const int img = tid / 10;
        const int o   = tid - img * 10;
        if (i0 + img < N) {
            const float* lg = s + SH_IMG0 + img * IMG_STRIDE + PLG;
            out[(i0 + img) * 10 + o] = lg[o] - lg[12];
        }
    }
}

extern "C" void kernel_launch(void* const* d_in, const int* in_sizes, int n_in,
                              void* d_out, int out_size) {
    const float* x        = (const float*)d_in[0];
    const float* kf_w1    = (const float*)d_in[1];
    const float* kf_b1    = (const float*)d_in[2];
    const float* kf_w2    = (const float*)d_in[3];
    const float* kf_b2    = (const float*)d_in[4];
    const float* kf_fc1_w = (const float*)d_in[5];
    const float* kf_fc1_b = (const float*)d_in[6];
    const float* kf_fc2_w = (const float*)d_in[7];
    const float* kf_fc2_b = (const float*)d_in[8];
    const float* conv2_w  = (const float*)d_in[9];
    const float* conv2_b  = (const float*)d_in[10];
    const float* fc1_w    = (const float*)d_in[11];
    const float* fc1_b    = (const float*)d_in[12];
    const float* fc2_w    = (const float*)d_in[13];
    const float* fc2_b    = (const float*)d_in[14];
    float* out = (float*)d_out;

    const int N = in_sizes[0] / 784;
    const int grid = (N + 1) / 2;
    cudaFuncSetAttribute(fused_net_kernel,
                         cudaFuncAttributeMaxDynamicSharedMemorySize, SMEM_BYTES);
    fused_net_kernel<<<grid, TPB, SMEM_BYTES>>>(x, kf_w1, kf_b1, kf_w2, kf_b2,
                                                kf_fc1_w, kf_fc1_b, kf_fc2_w, kf_fc2_b,
                                                conv2_w, conv2_b, fc1_w, fc1_b,
                                                fc2_w, fc2_b, out, N);
}

// round 7
// speedup vs baseline: 1.4787x; 1.4787x over previous
#include <cuda_runtime.h>
#include <math.h>

#define TPB 352
typedef unsigned long long u64;

// ---- packed fp32x2 helpers (sm_103a) ----
__device__ __forceinline__ u64 packdup(float a) {
    u64 r; asm("mov.b64 %0,{%1,%1};" : "=l"(r) : "f"(a)); return r;
}
__device__ __forceinline__ u64 fma2(u64 a, u64 b, u64 c) {
    u64 d; asm("fma.rn.f32x2 %0,%1,%2,%3;" : "=l"(d) : "l"(a), "l"(b), "l"(c)); return d;
}
__device__ __forceinline__ void unpk(u64 x, float& lo, float& hi) {
    asm("mov.b64 {%0,%1},%2;" : "=f"(lo), "=f"(hi) : "l"(x));
}

// ---- shared memory layout (floats) ----
#define OFF_W1P 0        // [4 pair][49] x2       (392)
#define OFF_W2P 392      // [5 pair][8ci][25] x2  (2000)
#define OFF_CWP 2392     // [10 pair][10ci][25]x2 (5000)
#define OFF_B1P 7392     // (8)
#define OFF_B2P 7400     // (10)
#define OFF_CBP 7410     // (20) -> 7430 pad 7432
#define OFF_K1T 7432     // kf_fc1_w^T [90][33]   (2970)
#define OFF_K2T 10402    // kf_fc2_w^T [32][41]   (1312)
#define OFF_F2T 11714    // fc2_w^T    [50][11]   (550) -> 12264 pad 12272
// per-image blocks (x2)
#define SH_IMG0 12272
#define IMG_STRIDE 3176
#define PX   0                // [28][28] (784)
#define PBUF 784              // pooled1 [8][11][12]=1056 / pooled3 [10][13][14]=1820
#define PF   2604             // (90)
#define PH   2694             // (32)
#define PK   2726             // (40) -> 2766 pad 2768
#define PP4  2768             // [20][4][4] (320)
#define PY1  3088             // (64)
#define PLG  3152             // (16) -> 3168
#define SMEM_FLOATS (SH_IMG0 + 2 * IMG_STRIDE)
#define SMEM_BYTES  (SMEM_FLOATS * 4)

__global__ __launch_bounds__(TPB, 3) void fused_net_kernel(
    const float* __restrict__ x,
    const float* __restrict__ kf_w1, const float* __restrict__ kf_b1,
    const float* __restrict__ kf_w2, const float* __restrict__ kf_b2,
    const float* __restrict__ kf_fc1_w, const float* __restrict__ kf_fc1_b,
    const float* __restrict__ kf_fc2_w, const float* __restrict__ kf_fc2_b,
    const float* __restrict__ conv2_w, const float* __restrict__ conv2_b,
    const float* __restrict__ fc1_w, const float* __restrict__ fc1_b,
    const float* __restrict__ fc2_w, const float* __restrict__ fc2_b,
    float* __restrict__ out, int N)
{
    extern __shared__ __align__(16) float s[];

    const int bn  = blockIdx.x;
    const int tid = threadIdx.x;
    const int i0  = 2 * bn;

    // ================= Stage 0: stage inputs into smem =================
    {
        #pragma unroll
        for (int img = 0; img < 2; img++) {
            if (i0 + img < N) {
                const float4* x4 = (const float4*)(x + (i0 + img) * 784);
                float4* sx4 = (float4*)(s + SH_IMG0 + img * IMG_STRIDE + PX);
                for (int i = tid; i < 196; i += TPB) sx4[i] = x4[i];
            }
        }
        for (int i = tid; i < 392; i += TPB) {
            int c = i / 49, q = i - c * 49;
            s[OFF_W1P + (((c >> 1) * 49 + q) << 1) + (c & 1)] = kf_w1[i];
        }
        for (int i = tid; i < 2000; i += TPB) {
            int c = i / 200, r = i - c * 200;
            s[OFF_W2P + (((c >> 1) * 200 + r) << 1) + (c & 1)] = kf_w2[i];
        }
        for (int i = tid; i < 5000; i += TPB) {
            int c = i / 250, r = i - c * 250;
            s[OFF_CWP + (((c >> 1) * 250 + r) << 1) + (c & 1)] = conv2_w[i];
        }
        if (tid < 8)  s[OFF_B1P + tid] = kf_b1[tid];
        if (tid < 10) s[OFF_B2P + tid] = kf_b2[tid];
        if (tid < 20) s[OFF_CBP + tid] = conv2_b[tid];
        for (int i = tid; i < 2880; i += TPB) {
            int o = i / 90, q = i - o * 90;
            s[OFF_K1T + q * 33 + o] = kf_fc1_w[i];
        }
        for (int i = tid; i < 1280; i += TPB) {
            int o = i >> 5, q = i & 31;
            s[OFF_K2T + q * 41 + o] = kf_fc2_w[i];
        }
        for (int i = tid; i < 500; i += TPB) {
            int o = i / 50, q = i - o * 50;
            s[OFF_F2T + q * 11 + o] = fc2_w[i];
        }
    }
    __syncthreads();

    // ===== Stage 1: conv7x7 (1->8) + pool + relu -> pooled1 [8][11][12pad] =====
    // thread = (u, cp) with cp FASTEST: lanes sharing u broadcast activation reads.
    {
        const int cp   = tid & 3;
        const int u    = tid >> 2;       // 0..87
        const int img  = u / 44;
        const int rem2 = u - img * 44;
        const int pi   = rem2 >> 2;
        const int q    = rem2 & 3;
        const int nc   = (q < 3) ? 3 : 2;
        const float* sx = s + SH_IMG0 + img * IMG_STRIDE + PX;
        const u64* wp = (const u64*)(s + OFF_W1P) + cp * 49;
        const u64 bias = ((const u64*)(s + OFF_B1P))[cp];
        u64 A[3][4];
        #pragma unroll
        for (int k = 0; k < 3; k++)
            #pragma unroll
            for (int w = 0; w < 4; w++) A[k][w] = bias;

        #pragma unroll
        for (int r = 0; r < 8; r++) {
            const float2* row = (const float2*)(sx + (2 * pi + r) * 28 + 6 * q);
            u64 pd[12];
            #pragma unroll
            for (int j = 0; j < 6; j++) {
                float2 f = row[j];
                pd[2 * j]     = packdup(f.x);
                pd[2 * j + 1] = packdup(f.y);
            }
            if (r < 7) {
                #pragma unroll
                for (int v = 0; v < 7; v++) {
                    const u64 w = wp[r * 7 + v];
                    #pragma unroll
                    for (int k = 0; k < 3; k++) {
                        A[k][0] = fma2(pd[2 * k + v],     w, A[k][0]);
                        A[k][1] = fma2(pd[2 * k + v + 1], w, A[k][1]);
                    }
                }
            }
            if (r >= 1) {
                #pragma unroll
                for (int v = 0; v < 7; v++) {
                    const u64 w = wp[(r - 1) * 7 + v];
                    #pragma unroll
                    for (int k = 0; k < 3; k++) {
                        A[k][2] = fma2(pd[2 * k + v],     w, A[k][2]);
                        A[k][3] = fma2(pd[2 * k + v + 1], w, A[k][3]);
                    }
                }
            }
        }
        float* buf = s + SH_IMG0 + img * IMG_STRIDE + PBUF;
        #pragma unroll
        for (int k = 0; k < 3; k++) {
            if (k < nc) {
                float p0, p1, q0, q1, r0, r1, t0, t1;
                unpk(A[k][0], p0, p1); unpk(A[k][1], q0, q1);
                unpk(A[k][2], r0, r1); unpk(A[k][3], t0, t1);
                const int pj = 3 * q + k;
                buf[(2 * cp)     * 132 + pi * 12 + pj] =
                    fmaxf(fmaxf(fmaxf(p0, q0), fmaxf(r0, t0)), 0.0f);
                buf[(2 * cp + 1) * 132 + pi * 12 + pj] =
                    fmaxf(fmaxf(fmaxf(p1, q1), fmaxf(r1, t1)), 0.0f);
            }
        }
    }
    __syncthreads();

    // ===== Stage 2: conv5x5 (8->10) + pool + relu -> f [10][3][3] =====
    // thread = (p, half), p = (pos-group, cp) with cp fast -> activation broadcast.
    if (tid < 192) {
        const int p    = tid >> 1;
        const int half = tid & 1;
        const bool valid = p < 90;
        const int pp   = valid ? p : 0;
        const int cp   = pp % 5;
        const int rest = pp / 5;          // 0..17
        const int img  = rest / 9;
        const int pos  = rest - img * 9;
        const int pi   = pos / 3;
        const int pj   = pos - pi * 3;
        const float* buf = s + SH_IMG0 + img * IMG_STRIDE + PBUF;
        const u64 bias = ((const u64*)(s + OFF_B2P))[cp];
        u64 A[4];
        #pragma unroll
        for (int k = 0; k < 4; k++) A[k] = half ? 0ull : bias;
        #pragma unroll
        for (int cc = 0; cc < 4; cc++) {
            const int ci = 4 * half + cc;
            const u64* wp = (const u64*)(s + OFF_W2P) + (cp * 8 + ci) * 25;
            #pragma unroll
            for (int r = 0; r < 6; r++) {
                const float2* row = (const float2*)(buf + ci * 132 + (2 * pi + r) * 12 + 2 * pj);
                u64 pd[6];
                #pragma unroll
                for (int j = 0; j < 3; j++) {
                    float2 f = row[j];
                    pd[2 * j]     = packdup(f.x);
                    pd[2 * j + 1] = packdup(f.y);
                }
                if (r < 5) {
                    #pragma unroll
                    for (int v = 0; v < 5; v++) {
                        const u64 wv = wp[r * 5 + v];
                        A[0] = fma2(pd[v],     wv, A[0]);
                        A[1] = fma2(pd[v + 1], wv, A[1]);
                    }
                }
                if (r >= 1) {
                    #pragma unroll
                    for (int v = 0; v < 5; v++) {
                        const u64 wv = wp[(r - 1) * 5 + v];
                        A[2] = fma2(pd[v],     wv, A[2]);
                        A[3] = fma2(pd[v + 1], wv, A[3]);
                    }
                }
            }
        }
        float me = -INFINITY, mo = -INFINITY;
        #pragma unroll
        for (int k = 0; k < 4; k++) {
            float lo, hi;
            unpk(A[k], lo, hi);
            lo += __shfl_xor_sync(0xffffffffu, lo, 1);
            hi += __shfl_xor_sync(0xffffffffu, hi, 1);
            me = fmaxf(me, lo);
            mo = fmaxf(mo, hi);
        }
        if (valid) {
            float* f = s + SH_IMG0 + img * IMG_STRIDE + PF;
            if (half == 0) f[(2 * cp)     * 9 + pos] = fmaxf(me, 0.0f);
            else           f[(2 * cp + 1) * 9 + pos] = fmaxf(mo, 0.0f);
        }
    }
    __syncthreads();

    // ===== Stage 3a: hypernet fc1 90->32 relu =====
    if (tid < 64) {
        const int img = tid >> 5;
        const int o   = tid & 31;
        const float* f = s + SH_IMG0 + img * IMG_STRIDE + PF;
        float acc = kf_fc1_b[o];
        #pragma unroll 6
        for (int q = 0; q < 90; q++)
            acc = fmaf(f[q], s[OFF_K1T + q * 33 + o], acc);
        s[SH_IMG0 + img * IMG_STRIDE + PH + o] = fmaxf(acc, 0.0f);
    }
    __syncthreads();
    // ===== Stage 3b: hypernet fc2 32->40 =====
    if (tid < 80) {
        const int img = tid / 40;
        const int o   = tid - img * 40;
        const float* h = s + SH_IMG0 + img * IMG_STRIDE + PH;
        float acc = kf_fc2_b[o];
        #pragma unroll
        for (int q = 0; q < 32; q++)
            acc = fmaf(h[q], s[OFF_K2T + q * 41 + o], acc);
        s[SH_IMG0 + img * IMG_STRIDE + PK + o] = acc;
    }
    __syncthreads();

    // ===== Stage 4: dynamic 2x2 conv + pool + relu -> pooled3 [10][13][14pad] =====
    // c fastest -> 10 lanes share each x window (broadcast).
    for (int it = tid; it < 3380; it += TPB) {
        const int c   = it % 10;
        const int pim = it / 10;          // 0..337
        const int img = pim / 169;
        const int rem = pim - img * 169;
        const int pi  = rem / 13;
        const int pj  = rem - pi * 13;
        const float* base = s + SH_IMG0 + img * IMG_STRIDE;
        const float k00 = base[PK + c * 4 + 0];
        const float k01 = base[PK + c * 4 + 1];
        const float k10 = base[PK + c * 4 + 2];
        const float k11 = base[PK + c * 4 + 3];
        float a[3][3];
        #pragma unroll
        for (int u2 = 0; u2 < 3; u2++) {
            const float2 f01 = *(const float2*)(base + PX + (2 * pi + u2) * 28 + 2 * pj);
            a[u2][0] = f01.x; a[u2][1] = f01.y;
            a[u2][2] = base[PX + (2 * pi + u2) * 28 + 2 * pj + 2];
        }
        float m = -INFINITY;
        #pragma unroll
        for (int di = 0; di < 2; di++)
            #pragma unroll
            for (int dj = 0; dj < 2; dj++) {
                float cv = a[di][dj] * k00;
                cv = fmaf(a[di][dj + 1],     k01, cv);
                cv = fmaf(a[di + 1][dj],     k10, cv);
                cv = fmaf(a[di + 1][dj + 1], k11, cv);
                m = fmaxf(m, cv);
            }
        s[SH_IMG0 + img * IMG_STRIDE + PBUF + c * 182 + pi * 14 + pj] = fmaxf(m, 0.0f);
    }
    __syncthreads();

    // ===== Stage 5: conv5x5 (10->20) + pool + relu -> pooled4 [20][4][4] =====
    // 640 units = cp(10) x img(2) x cih(2) x pos(16), two passes of 320.
    // cih on lane bit 4 (shfl_xor(16) partner); cp cycles fastest within halves.
    #pragma unroll
    for (int pass = 0; pass < 2; pass++) {
        if (tid < 320) {
            const int lane = tid & 31;
            const int w    = tid >> 5;        // 0..9
            const int cih  = (lane >> 4) & 1;
            const int l4   = lane & 15;
            const int G    = pass * 160 + w * 16 + l4;   // 0..319
            const int cp   = G % 10;
            const int gg   = G / 10;          // 0..31
            const int img  = gg >> 4;
            const int pos  = gg & 15;
            const int pi   = pos >> 2;
            const int pj   = pos & 3;
            const float* buf = s + SH_IMG0 + img * IMG_STRIDE + PBUF;
            const u64 bias = ((const u64*)(s + OFF_CBP))[cp];
            u64 A[4];
            #pragma unroll
            for (int k = 0; k < 4; k++) A[k] = cih ? 0ull : bias;

            #pragma unroll
            for (int cc = 0; cc < 5; cc++) {
                const int ci = 5 * cih + cc;
                const u64* wp = (const u64*)(s + OFF_CWP) + (cp * 10 + ci) * 25;
                #pragma unroll
                for (int r = 0; r < 6; r++) {
                    const float2* row = (const float2*)(buf + ci * 182 + (2 * pi + r) * 14 + 2 * pj);
                    u64 pd[6];
                    #pragma unroll
                    for (int j = 0; j < 3; j++) {
                        float2 f = row[j];
                        pd[2 * j]     = packdup(f.x);
                        pd[2 * j + 1] = packdup(f.y);
                    }
                    if (r < 5) {
                        #pragma unroll
                        for (int v = 0; v < 5; v++) {
                            const u64 wv = wp[r * 5 + v];
                            A[0] = fma2(pd[v],     wv, A[0]);
                            A[1] = fma2(pd[v + 1], wv, A[1]);
                        }
                    }
                    if (r >= 1) {
                        #pragma unroll
                        for (int v = 0; v < 5; v++) {
                            const u64 wv = wp[(r - 1) * 5 + v];
                            A[2] = fma2(pd[v],     wv, A[2]);
                            A[3] = fma2(pd[v + 1], wv, A[3]);
                        }
                    }
                }
            }
            float m0 = -INFINITY, m1 = -INFINITY;
            #pragma unroll
            for (int k = 0; k < 4; k++) {
                float lo, hi;
                unpk(A[k], lo, hi);
                lo += __shfl_xor_sync(0xffffffffu, lo, 16);
                hi += __shfl_xor_sync(0xffffffffu, hi, 16);
                m0 = fmaxf(m0, lo);
                m1 = fmaxf(m1, hi);
            }
            if (cih == 0) {
                float* p4 = s + SH_IMG0 + img * IMG_STRIDE + PP4;
                p4[(2 * cp)     * 16 + pi * 4 + pj] = fmaxf(m0, 0.0f);
                p4[(2 * cp + 1) * 16 + pi * 4 + pj] = fmaxf(m1, 0.0f);
            }
        }
    }
    __syncthreads();

    // ===== Stage 6: fc1 320->50 relu, warp per (img,o) =====
    {
        const int warp = tid >> 5;
        const int lane = tid & 31;
        for (int u = warp; u < 100; u += (TPB / 32)) {
            const int img = u / 50;
            const int o   = u - img * 50;
            const float4* wr = (const float4*)(fc1_w + o * 320);
            const float4* pr = (const float4*)(s + SH_IMG0 + img * IMG_STRIDE + PP4);
            float acc = 0.0f;
            #pragma unroll
            for (int k = 0; k < 3; k++) {
                const int i = lane + 32 * k;
                if (i < 80) {
                    float4 w4 = wr[i];
                    float4 p4 = pr[i];
                    acc = fmaf(w4.x, p4.x, fmaf(w4.y, p4.y,
                          fmaf(w4.z, p4.z, fmaf(w4.w, p4.w, acc))));
                }
            }
            #pragma unroll
            for (int off = 16; off > 0; off >>= 1)
                acc += __shfl_xor_sync(0xffffffffu, acc, off);
            if (lane == 0)
                s[SH_IMG0 + img * IMG_STRIDE + PY1 + o] = fmaxf(acc + fc1_b[o], 0.0f);
        }
    }
    __syncthreads();

    // ===== Stage 7: fc2 50->10 + log_softmax =====
    if (tid < 20) {
        const int img = tid / 10;
        const int o   = tid - img * 10;
        const float* y1 = s + SH_IMG0 + img * IMG_STRIDE + PY1;
        float acc = fc2_b[o];
        #pragma unroll 10
        for (int q = 0; q < 50; q++)
            acc = fmaf(y1[q], s[OFF_F2T + q * 11 + o], acc);
        s[SH_IMG0 + img * IMG_STRIDE + PLG + o] = acc;
    }
    __syncthreads();
    if (tid < 2) {
        const float* lg = s + SH_IMG0 + tid * IMG_STRIDE + PLG;
        float mx = lg[0];
        #pragma unroll
        for (int q = 1; q < 10; q++) mx = fmaxf(mx, lg[q]);
        float sum = 0.0f;
        #pragma unroll
        for (int q = 0; q < 10; q++) sum += expf(lg[q] - mx);
        s[SH_IMG0 + tid * IMG_STRIDE + PLG + 12] = mx + logf(sum);
    }
    __syncthreads();
    if (tid < 20) {
        const int img = tid / 10;
        const int o   = tid - img * 10;
        if (i0 + img < N) {
            const float* lg = s + SH_IMG0 + img * IMG_STRIDE + PLG;
            out[(i0 + img) * 10 + o] = lg[o] - lg[12];
        }
    }
}

extern "C" void kernel_launch(void* const* d_in, const int* in_sizes, int n_in,
                              void* d_out, int out_size) {
    const float* x        = (const float*)d_in[0];
    const float* kf_w1    = (const float*)d_in[1];
    const float* kf_b1    = (const float*)d_in[2];
    const float* kf_w2    = (const float*)d_in[3];
    const float* kf_b2    = (const float*)d_in[4];
    const float* kf_fc1_w = (const float*)d_in[5];
    const float* kf_fc1_b = (const float*)d_in[6];
    const float* kf_fc2_w = (const float*)d_in[7];
    const float* kf_fc2_b = (const float*)d_in[8];
    const float* conv2_w  = (const float*)d_in[9];
    const float* conv2_b  = (const float*)d_in[10];
    const float* fc1_w    = (const float*)d_in[11];
    const float* fc1_b    = (const float*)d_in[12];
    const float* fc2_w    = (const float*)d_in[13];
    const float* fc2_b    = (const float*)d_in[14];
    float* out = (float*)d_out;

    const int N = in_sizes[0] / 784;
    const int grid = (N + 1) / 2;
    cudaFuncSetAttribute(fused_net_kernel,
                         cudaFuncAttributeMaxDynamicSharedMemorySize, SMEM_BYTES);
    fused_net_kernel<<<grid, TPB, SMEM_BYTES>>>(x, kf_w1, kf_b1, kf_w2, kf_b2,
                                                kf_fc1_w, kf_fc1_b, kf_fc2_w, kf_fc2_b,
                                                conv2_w, conv2_b, fc1_w, fc1_b,
                                                fc2_w, fc2_b, out, N);
}

// round 8
// speedup vs baseline: 1.6302x; 1.1025x over previous
#include <cuda_runtime.h>
#include <math.h>

#define TPB 352
typedef unsigned long long u64;

// ---- packed fp32x2 helpers (sm_103a) ----
__device__ __forceinline__ u64 packdup(float a) {
    u64 r; asm("mov.b64 %0,{%1,%1};" : "=l"(r) : "f"(a)); return r;
}
__device__ __forceinline__ u64 fma2(u64 a, u64 b, u64 c) {
    u64 d; asm("fma.rn.f32x2 %0,%1,%2,%3;" : "=l"(d) : "l"(a), "l"(b), "l"(c)); return d;
}
__device__ __forceinline__ void unpk(u64 x, float& lo, float& hi) {
    asm("mov.b64 {%0,%1},%2;" : "=f"(lo), "=f"(hi) : "l"(x));
}

// ---- shared memory layout (floats) ----
#define OFF_W1P 0        // [4 pair][49] x2       (392)
#define OFF_W2P 392      // [5 pair][8ci][25] x2  (2000)
#define OFF_CWP 2392     // [10 pair][10ci][25]x2 (5000)
#define OFF_B1P 7392     // (8)
#define OFF_B2P 7400     // (10)
#define OFF_CBP 7410     // (20) -> 7430 pad 7432
// per-image blocks (x2)
#define SH_IMG0 7432
#define IMG_STRIDE 3176
#define PX   0                // [28][28] (784)
#define PBUF 784              // pooled1 [8][11][12]=1056 / pooled3 [10][13][14]=1820
#define PF   2604             // (90)
#define PH   2694             // (32)
#define PK   2726             // (40) -> 2766 pad 2768
#define PP4  2768             // [20][4][4] (320)
#define PY1  3088             // (64)
#define PLG  3152             // (16) -> 3168
#define SMEM_FLOATS (SH_IMG0 + 2 * IMG_STRIDE)
#define SMEM_BYTES  (SMEM_FLOATS * 4)

__global__ __launch_bounds__(TPB, 4) void fused_net_kernel(
    const float* __restrict__ x,
    const float* __restrict__ kf_w1, const float* __restrict__ kf_b1,
    const float* __restrict__ kf_w2, const float* __restrict__ kf_b2,
    const float* __restrict__ kf_fc1_w, const float* __restrict__ kf_fc1_b,
    const float* __restrict__ kf_fc2_w, const float* __restrict__ kf_fc2_b,
    const float* __restrict__ conv2_w, const float* __restrict__ conv2_b,
    const float* __restrict__ fc1_w, const float* __restrict__ fc1_b,
    const float* __restrict__ fc2_w, const float* __restrict__ fc2_b,
    float* __restrict__ out, int N)
{
    extern __shared__ __align__(16) float s[];

    const int bn  = blockIdx.x;
    const int tid = threadIdx.x;
    const int i0  = 2 * bn;
    const int warp = tid >> 5;
    const int lane = tid & 31;

    // ================= Stage 0: stage inputs into smem =================
    {
        #pragma unroll
        for (int img = 0; img < 2; img++) {
            if (i0 + img < N) {
                const float4* x4 = (const float4*)(x + (i0 + img) * 784);
                float4* sx4 = (float4*)(s + SH_IMG0 + img * IMG_STRIDE + PX);
                for (int i = tid; i < 196; i += TPB) sx4[i] = x4[i];
            }
        }
        for (int i = tid; i < 392; i += TPB) {
            int c = i / 49, q = i - c * 49;
            s[OFF_W1P + (((c >> 1) * 49 + q) << 1) + (c & 1)] = kf_w1[i];
        }
        for (int i = tid; i < 2000; i += TPB) {
            int c = i / 200, r = i - c * 200;
            s[OFF_W2P + (((c >> 1) * 200 + r) << 1) + (c & 1)] = kf_w2[i];
        }
        for (int i = tid; i < 5000; i += TPB) {
            int c = i / 250, r = i - c * 250;
            s[OFF_CWP + (((c >> 1) * 250 + r) << 1) + (c & 1)] = conv2_w[i];
        }
        if (tid < 8)  s[OFF_B1P + tid] = kf_b1[tid];
        if (tid < 10) s[OFF_B2P + tid] = kf_b2[tid];
        if (tid < 20) s[OFF_CBP + tid] = conv2_b[tid];
    }
    __syncthreads();

    // ===== Stage 1: conv7x7 (1->8) + pool + relu -> pooled1 [8][11][12pad] =====
    // unit = (img, channel-pair, pooled pos). 968 units, light 4-acc body.
    for (int u = tid; u < 968; u += TPB) {
        const int img = u / 484;
        const int t   = u - img * 484;
        const int cp  = t / 121;
        const int r2  = t - cp * 121;
        const int pi  = r2 / 11;
        const int pj  = r2 - pi * 11;
        const float* sx = s + SH_IMG0 + img * IMG_STRIDE + PX;
        const u64* wp = (const u64*)(s + OFF_W1P) + cp * 49;
        const u64 bias = ((const u64*)(s + OFF_B1P))[cp];
        u64 a00 = bias, a01 = bias, a10 = bias, a11 = bias;
        #pragma unroll
        for (int r = 0; r < 8; r++) {
            const float2* row = (const float2*)(sx + (2 * pi + r) * 28 + 2 * pj);
            u64 pd[8];
            #pragma unroll
            for (int j = 0; j < 4; j++) {
                float2 f = row[j];
                pd[2 * j]     = packdup(f.x);
                pd[2 * j + 1] = packdup(f.y);
            }
            if (r < 7) {
                const u64* w = wp + r * 7;
                #pragma unroll
                for (int v = 0; v < 7; v++) {
                    const u64 wv = w[v];
                    a00 = fma2(pd[v],     wv, a00);
                    a01 = fma2(pd[v + 1], wv, a01);
                }
            }
            if (r >= 1) {
                const u64* w = wp + (r - 1) * 7;
                #pragma unroll
                for (int v = 0; v < 7; v++) {
                    const u64 wv = w[v];
                    a10 = fma2(pd[v],     wv, a10);
                    a11 = fma2(pd[v + 1], wv, a11);
                }
            }
        }
        float p0, p1, q0, q1, r0, r1, t0, t1;
        unpk(a00, p0, p1); unpk(a01, q0, q1); unpk(a10, r0, r1); unpk(a11, t0, t1);
        float m0 = fmaxf(fmaxf(p0, q0), fmaxf(r0, t0));
        float m1 = fmaxf(fmaxf(p1, q1), fmaxf(r1, t1));
        float* buf = s + SH_IMG0 + img * IMG_STRIDE + PBUF;
        buf[(2 * cp)     * 132 + pi * 12 + pj] = fmaxf(m0, 0.0f);
        buf[(2 * cp + 1) * 132 + pi * 12 + pj] = fmaxf(m1, 0.0f);
    }
    __syncthreads();

    // ===== Stage 2: conv5x5 (8->10) + pool + relu -> f [10][3][3] =====
    // thread = (unit, ci-half); halves combined by shfl_xor(1). 180(+12) threads.
    if (tid < 192) {
        const int uu   = tid >> 1;
        const int half = tid & 1;
        const bool valid = uu < 90;
        const int u   = valid ? uu : 0;
        const int img = u / 45;
        const int t   = u - img * 45;
        const int cp  = t / 9;
        const int pos = t - cp * 9;
        const int pi  = pos / 3;
        const int pj  = pos - pi * 3;
        const float* buf = s + SH_IMG0 + img * IMG_STRIDE + PBUF;
        const u64 bias = ((const u64*)(s + OFF_B2P))[cp];
        u64 A[4];
        #pragma unroll
        for (int k = 0; k < 4; k++) A[k] = half ? 0ull : bias;
        #pragma unroll
        for (int cc = 0; cc < 4; cc++) {
            const int ci = 4 * half + cc;
            const u64* wp = (const u64*)(s + OFF_W2P) + (cp * 8 + ci) * 25;
            #pragma unroll
            for (int r = 0; r < 6; r++) {
                const float2* row = (const float2*)(buf + ci * 132 + (2 * pi + r) * 12 + 2 * pj);
                u64 pd[6];
                #pragma unroll
                for (int j = 0; j < 3; j++) {
                    float2 f = row[j];
                    pd[2 * j]     = packdup(f.x);
                    pd[2 * j + 1] = packdup(f.y);
                }
                if (r < 5) {
                    #pragma unroll
                    for (int v = 0; v < 5; v++) {
                        const u64 wv = wp[r * 5 + v];
                        A[0] = fma2(pd[v],     wv, A[0]);
                        A[1] = fma2(pd[v + 1], wv, A[1]);
                    }
                }
                if (r >= 1) {
                    #pragma unroll
                    for (int v = 0; v < 5; v++) {
                        const u64 wv = wp[(r - 1) * 5 + v];
                        A[2] = fma2(pd[v],     wv, A[2]);
                        A[3] = fma2(pd[v + 1], wv, A[3]);
                    }
                }
            }
        }
        float me = -INFINITY, mo = -INFINITY;
        #pragma unroll
        for (int k = 0; k < 4; k++) {
            float lo, hi;
            unpk(A[k], lo, hi);
            lo += __shfl_xor_sync(0xffffffffu, lo, 1);
            hi += __shfl_xor_sync(0xffffffffu, hi, 1);
            me = fmaxf(me, lo);
            mo = fmaxf(mo, hi);
        }
        if (valid) {
            float* f = s + SH_IMG0 + img * IMG_STRIDE + PF;
            if (half == 0) f[(2 * cp)     * 9 + pos] = fmaxf(me, 0.0f);
            else           f[(2 * cp + 1) * 9 + pos] = fmaxf(mo, 0.0f);
        }
    }
    __syncthreads();

    // ===== Stage 3a: hypernet fc1 90->32 relu — warp per output, global weights =====
    for (int u = warp; u < 64; u += (TPB / 32)) {
        const int img = u >> 5;
        const int o   = u & 31;
        const float* f  = s + SH_IMG0 + img * IMG_STRIDE + PF;
        const float* wr = kf_fc1_w + o * 90;
        float acc = 0.0f;
        #pragma unroll
        for (int k = 0; k < 3; k++) {
            const int q = lane + 32 * k;
            if (q < 90) acc = fmaf(f[q], wr[q], acc);
        }
        #pragma unroll
        for (int off = 16; off > 0; off >>= 1)
            acc += __shfl_xor_sync(0xffffffffu, acc, off);
        if (lane == 0)
            s[SH_IMG0 + img * IMG_STRIDE + PH + o] = fmaxf(acc + kf_fc1_b[o], 0.0f);
    }
    __syncthreads();

    // ===== Stage 3b: hypernet fc2 32->40 — warp per output, global weights =====
    for (int u = warp; u < 80; u += (TPB / 32)) {
        const int img = u / 40;
        const int o   = u - img * 40;
        const float* h = s + SH_IMG0 + img * IMG_STRIDE + PH;
        float acc = h[lane] * kf_fc2_w[o * 32 + lane];
        #pragma unroll
        for (int off = 16; off > 0; off >>= 1)
            acc += __shfl_xor_sync(0xffffffffu, acc, off);
        if (lane == 0)
            s[SH_IMG0 + img * IMG_STRIDE + PK + o] = acc + kf_fc2_b[o];
    }
    __syncthreads();

    // ===== Stage 4: dynamic 2x2 conv + pool + relu -> pooled3 [10][13][14pad] =====
    for (int it = tid; it < 3380; it += TPB) {
        const int img = it / 1690;
        const int t   = it - img * 1690;
        const int c   = t / 169;
        const int rem = t - c * 169;
        const int pi  = rem / 13;
        const int pj  = rem - pi * 13;
        const float* base = s + SH_IMG0 + img * IMG_STRIDE;
        const float k00 = base[PK + c * 4 + 0];
        const float k01 = base[PK + c * 4 + 1];
        const float k10 = base[PK + c * 4 + 2];
        const float k11 = base[PK + c * 4 + 3];
        float a[3][3];
        #pragma unroll
        for (int u2 = 0; u2 < 3; u2++) {
            const float2 f01 = *(const float2*)(base + PX + (2 * pi + u2) * 28 + 2 * pj);
            a[u2][0] = f01.x; a[u2][1] = f01.y;
            a[u2][2] = base[PX + (2 * pi + u2) * 28 + 2 * pj + 2];
        }
        float m = -INFINITY;
        #pragma unroll
        for (int di = 0; di < 2; di++)
            #pragma unroll
            for (int dj = 0; dj < 2; dj++) {
                float cv = a[di][dj] * k00;
                cv = fmaf(a[di][dj + 1],     k01, cv);
                cv = fmaf(a[di + 1][dj],     k10, cv);
                cv = fmaf(a[di + 1][dj + 1], k11, cv);
                m = fmaxf(m, cv);
            }
        s[SH_IMG0 + img * IMG_STRIDE + PBUF + c * 182 + pi * 14 + pj] = fmaxf(m, 0.0f);
    }
    __syncthreads();

    // ===== Stage 5: conv5x5 (10->20) + pool + relu -> pooled4 [20][4][4] =====
    // unit = (img, cp, pos). 320 units, light 4-acc body, full 10 ci.
    if (tid < 320) {
        const int img = tid / 160;
        const int t   = tid - img * 160;
        const int cp  = t / 16;
        const int pos = t - cp * 16;
        const int pi  = pos / 4;
        const int pj  = pos - pi * 4;
        const float* buf = s + SH_IMG0 + img * IMG_STRIDE + PBUF;
        const u64 bias = ((const u64*)(s + OFF_CBP))[cp];
        u64 A[4] = {bias, bias, bias, bias};
        #pragma unroll 2
        for (int ci = 0; ci < 10; ci++) {
            const u64* wp = (const u64*)(s + OFF_CWP) + (cp * 10 + ci) * 25;
            #pragma unroll
            for (int r = 0; r < 6; r++) {
                const float2* row = (const float2*)(buf + ci * 182 + (2 * pi + r) * 14 + 2 * pj);
                u64 pd[6];
                #pragma unroll
                for (int j = 0; j < 3; j++) {
                    float2 f = row[j];
                    pd[2 * j]     = packdup(f.x);
                    pd[2 * j + 1] = packdup(f.y);
                }
                if (r < 5) {
                    #pragma unroll
                    for (int v = 0; v < 5; v++) {
                        const u64 wv = wp[r * 5 + v];
                        A[0] = fma2(pd[v],     wv, A[0]);
                        A[1] = fma2(pd[v + 1], wv, A[1]);
                    }
                }
                if (r >= 1) {
                    #pragma unroll
                    for (int v = 0; v < 5; v++) {
                        const u64 wv = wp[(r - 1) * 5 + v];
                        A[2] = fma2(pd[v],     wv, A[2]);
                        A[3] = fma2(pd[v + 1], wv, A[3]);
                    }
                }
            }
        }
        float p0, p1, q0, q1, r0, r1, t0, t1;
        unpk(A[0], p0, p1); unpk(A[1], q0, q1); unpk(A[2], r0, r1); unpk(A[3], t0, t1);
        float m0 = fmaxf(fmaxf(p0, q0), fmaxf(r0, t0));
        float m1 = fmaxf(fmaxf(p1, q1), fmaxf(r1, t1));
        float* p4 = s + SH_IMG0 + img * IMG_STRIDE + PP4;
        p4[(2 * cp)     * 16 + pos] = fmaxf(m0, 0.0f);
        p4[(2 * cp + 1) * 16 + pos] = fmaxf(m1, 0.0f);
    }
    __syncthreads();

    // ===== Stage 6: fc1 320->50 relu, warp per (img,o), global weights =====
    for (int u = warp; u < 100; u += (TPB / 32)) {
        const int img = u / 50;
        const int o   = u - img * 50;
        const float4* wr = (const float4*)(fc1_w + o * 320);
        const float4* pr = (const float4*)(s + SH_IMG0 + img * IMG_STRIDE + PP4);
        float acc = 0.0f;
        #pragma unroll
        for (int k = 0; k < 3; k++) {
            const int i = lane + 32 * k;
            if (i < 80) {
                float4 w4 = wr[i];
                float4 p4 = pr[i];
                acc = fmaf(w4.x, p4.x, fmaf(w4.y, p4.y,
                      fmaf(w4.z, p4.z, fmaf(w4.w, p4.w, acc))));
            }
        }
        #pragma unroll
        for (int off = 16; off > 0; off >>= 1)
            acc += __shfl_xor_sync(0xffffffffu, acc, off);
        if (lane == 0)
            s[SH_IMG0 + img * IMG_STRIDE + PY1 + o] = fmaxf(acc + fc1_b[o], 0.0f);
    }
    __syncthreads();

    // ===== Stage 7: fc2 50->10 — warp per (img,o), global weights =====
    for (int u = warp; u < 20; u += (TPB / 32)) {
        const int img = u / 10;
        const int o   = u - img * 10;
        const float* y1 = s + SH_IMG0 + img * IMG_STRIDE + PY1;
        const float* wr = fc2_w + o * 50;
        float acc = y1[lane] * wr[lane];
        const int q = lane + 32;
        if (q < 50) acc = fmaf(y1[q], wr[q], acc);
        #pragma unroll
        for (int off = 16; off > 0; off >>= 1)
            acc += __shfl_xor_sync(0xffffffffu, acc, off);
        if (lane == 0)
            s[SH_IMG0 + img * IMG_STRIDE + PLG + o] = acc + fc2_b[o];
    }
    __syncthreads();
    if (tid < 2) {
        const float* lg = s + SH_IMG0 + tid * IMG_STRIDE + PLG;
        float mx = lg[0];
        #pragma unroll
        for (int q = 1; q < 10; q++) mx = fmaxf(mx, lg[q]);
        float sum = 0.0f;
        #pragma unroll
        for (int q = 0; q < 10; q++) sum += expf(lg[q] - mx);
        s[SH_IMG0 + tid * IMG_STRIDE + PLG + 12] = mx + logf(sum);
    }
    __syncthreads();
    if (tid < 20) {
        const int img = tid / 10;
        const int o   = tid - img * 10;
        if (i0 + img < N) {
            const float* lg = s + SH_IMG0 + img * IMG_STRIDE + PLG;
            out[(i0 + img) * 10 + o] = lg[o] - lg[12];
        }
    }
}

extern "C" void kernel_launch(void* const* d_in, const int* in_sizes, int n_in,
                              void* d_out, int out_size) {
    const float* x        = (const float*)d_in[0];
    const float* kf_w1    = (const float*)d_in[1];
    const float* kf_b1    = (const float*)d_in[2];
    const float* kf_w2    = (const float*)d_in[3];
    const float* kf_b2    = (const float*)d_in[4];
    const float* kf_fc1_w = (const float*)d_in[5];
    const float* kf_fc1_b = (const float*)d_in[6];
    const float* kf_fc2_w = (const float*)d_in[7];
    const float* kf_fc2_b = (const float*)d_in[8];
    const float* conv2_w  = (const float*)d_in[9];
    const float* conv2_b  = (const float*)d_in[10];
    const float* fc1_w    = (const float*)d_in[11];
    const float* fc1_b    = (const float*)d_in[12];
    const float* fc2_w    = (const float*)d_in[13];
    const float* fc2_b    = (const float*)d_in[14];
    float* out = (float*)d_out;

    const int N = in_sizes[0] / 784;
    const int grid = (N + 1) / 2;
    cudaFuncSetAttribute(fused_net_kernel,
                         cudaFuncAttributeMaxDynamicSharedMemorySize, SMEM_BYTES);
    fused_net_kernel<<<grid, TPB, SMEM_BYTES>>>(x, kf_w1, kf_b1, kf_w2, kf_b2,
                                                kf_fc1_w, kf_fc1_b, kf_fc2_w, kf_fc2_b,
                                                conv2_w, conv2_b, fc1_w, fc1_b,
                                                fc2_w, fc2_b, out, N);
}